// round 11
// baseline (speedup 1.0000x reference)
#include <cuda_runtime.h>
#include <cuda_fp16.h>
#include <cuda_bf16.h>
#include <math.h>
#include <stdint.h>

#define B_BATCH 64
#define S_DIM   576
#define SH      288            // folded K (e/o each)
#define D_DIM   1024
#define AROWS   640            // padded rows per parity: [trunc | pad | M at 320..320+nM]
#define MOFF    320
#define NTILES  5120           // 8 colblocks * 10 (p,rowblock) * 64 batches
#define GRID_P  152

// ---------------- scratch (no allocs allowed) ----------------
__device__ float g_A2[2 * AROWS * SH];                 // fp32 [C | pad | M] per parity
__device__ float g_ClT[S_DIM * S_DIM];                 // ClT[i*L + k] = Cl[k,i]
__device__ char  g_A1l[2 * AROWS * SH];                // A limb1 (int8)
__device__ char  g_A2l[2 * AROWS * SH];                // A limb2
__device__ char  g_B1l[(size_t)2 * B_BATCH * D_DIM * SH];  // B limb1 [p][b][d][s]
__device__ char  g_B2l[(size_t)2 * B_BATCH * D_DIM * SH];  // B limb2
__device__ float g_SA[2 * AROWS];                      // per A-row scale
__device__ float g_SB[2 * B_BATCH * D_DIM];            // per B-row (d) scale
__device__ float g_y[(size_t)2 * B_BATCH * SH * D_DIM];    // ye / yo scratch

// ---------------- helpers ----------------
__device__ __forceinline__ uint32_t smem_u32(const void* p) {
    uint32_t a;
    asm("{ .reg .u64 t; cvta.to.shared.u64 t, %1; cvt.u32.u64 %0, t; }" : "=r"(a) : "l"(p));
    return a;
}
__device__ __forceinline__ void cp16(uint32_t dst, const void* src) {
    asm volatile("cp.async.cg.shared.global [%0], [%1], 16;" :: "r"(dst), "l"(src));
}
#define CP_COMMIT() asm volatile("cp.async.commit_group;" ::: "memory")
#define CP_WAIT1()  asm volatile("cp.async.wait_group 1;" ::: "memory")

__device__ __forceinline__ void ldsm_x4(uint32_t& r0, uint32_t& r1, uint32_t& r2,
                                        uint32_t& r3, uint32_t addr) {
    asm volatile("ldmatrix.sync.aligned.m8n8.x4.shared.b16 {%0,%1,%2,%3}, [%4];"
                 : "=r"(r0), "=r"(r1), "=r"(r2), "=r"(r3) : "r"(addr));
}
__device__ __forceinline__ void imma16832(int* d, const uint32_t* a,
                                          uint32_t b0, uint32_t b1) {
    asm volatile("mma.sync.aligned.m16n8k32.row.col.s32.s8.s8.s32 "
                 "{%0,%1,%2,%3}, {%4,%5,%6,%7}, {%8,%9}, {%0,%1,%2,%3};"
                 : "+r"(d[0]), "+r"(d[1]), "+r"(d[2]), "+r"(d[3])
                 : "r"(a[0]), "r"(a[1]), "r"(a[2]), "r"(a[3]), "r"(b0), "r"(b1));
}
#define SWZ(x) ((x) ^ (((x) >> 3) & 0x70))

// ---------------- basis build ----------------
__device__ __forceinline__ float dct_entry(int n, int k, int i) {
    float a   = (float)(M_PI / (double)n);
    float t   = a * ((float)i + 0.5f);
    float arg = t * (float)k;
    float c   = (float)cos((double)arg);
    float sc  = (k == 0) ? sqrtf(1.0f / (float)n) : sqrtf(2.0f / (float)n);
    return c * sc;
}

// Fills C-rows fp32, zeros everything else in g_A2, fills ClT.
__global__ void prep_basis(int L) {
    const int total1 = 2 * AROWS * SH;
    const int total  = total1 + L * L;
    for (int i = blockIdx.x * blockDim.x + threadIdx.x; i < total;
         i += gridDim.x * blockDim.x) {
        if (i < total1) {
            int p   = i / (AROWS * SH);
            int rem = i - p * (AROWS * SH);
            int row = rem / SH, s = rem - row * SH;
            int nTp = (L + 1 - p) >> 1;
            g_A2[i] = (row < nTp) ? dct_entry(S_DIM, 2 * row + p, s) : 0.0f;
        } else {
            int j = i - total1;
            int ii = j / L, k = j - ii * L;
            g_ClT[ii * L + k] = dct_entry(L, k, ii);
        }
    }
}

// Mp[l,s] = sum_{k=2j+p < L} Cl[k,l]*C[k,s] -> fp32 at g_A2[p][MOFF+l][s]
__global__ void build_M2(int L, int nM) {
    __shared__ float Ts[32][33];
    __shared__ float Cs[32][33];
    int p = blockIdx.z;
    int nK = (L + 1 - p) >> 1;
    const float* Cbase = g_A2 + (size_t)p * AROWS * SH;
    int tx = threadIdx.x, ty = threadIdx.y;       // 16x16
    int lin = ty * 16 + tx;
    int l0 = blockIdx.y * 32, s0 = blockIdx.x * 32;
    float acc00 = 0.f, acc01 = 0.f, acc10 = 0.f, acc11 = 0.f;
    for (int k0 = 0; k0 < nK; k0 += 32) {
        #pragma unroll
        for (int q = 0; q < 4; q++) {
            int e = lin + q * 256;
            int i = e >> 5, j = e & 31;
            int l = l0 + i, jj = k0 + j;
            Ts[i][j] = (l < nM && jj < nK) ? g_ClT[l * L + 2 * jj + p] : 0.0f;
            int j2 = k0 + i, s = s0 + j;
            Cs[i][j] = (j2 < nK && s < SH) ? Cbase[(size_t)j2 * SH + s] : 0.0f;
        }
        __syncthreads();
        #pragma unroll
        for (int kk = 0; kk < 32; kk++) {
            float a0 = Ts[ty * 2][kk], a1 = Ts[ty * 2 + 1][kk];
            float b0 = Cs[kk][tx * 2], b1 = Cs[kk][tx * 2 + 1];
            acc00 = fmaf(a0, b0, acc00); acc01 = fmaf(a0, b1, acc01);
            acc10 = fmaf(a1, b0, acc10); acc11 = fmaf(a1, b1, acc11);
        }
        __syncthreads();
    }
    float* Obase = g_A2 + (size_t)p * AROWS * SH + (size_t)MOFF * SH;
    int l = l0 + ty * 2, s = s0 + tx * 2;
    if (l < nM     && s < SH)     Obase[(size_t)l * SH + s]           = acc00;
    if (l < nM     && s + 1 < SH) Obase[(size_t)l * SH + s + 1]       = acc01;
    if (l + 1 < nM && s < SH)     Obase[(size_t)(l + 1) * SH + s]     = acc10;
    if (l + 1 < nM && s + 1 < SH) Obase[(size_t)(l + 1) * SH + s + 1] = acc11;
}

// One warp per A-row: rowmax -> scale -> 2-limb int8
__global__ void quantize_A() {
    int row = blockIdx.x * (blockDim.x / 32) + (threadIdx.x >> 5);
    if (row >= 2 * AROWS) return;
    int lane = threadIdx.x & 31;
    const float* src = g_A2 + (size_t)row * SH;
    float m = 0.0f;
    #pragma unroll
    for (int q = 0; q < 9; q++) m = fmaxf(m, fabsf(src[lane + 32 * q]));
    #pragma unroll
    for (int o = 16; o > 0; o >>= 1)
        m = fmaxf(m, __shfl_xor_sync(0xFFFFFFFF, m, o));
    float S = fmaxf(m, 1e-30f) / 127.0f;
    float inv = 127.0f / fmaxf(m, 1e-30f);
    if (lane == 0) g_SA[row] = S;
    #pragma unroll
    for (int q = 0; q < 9; q++) {
        int s = lane + 32 * q;
        float v = src[s];
        int b1 = __float2int_rn(v * inv);
        b1 = max(-127, min(127, b1));
        float r = fmaf((float)-b1, S, v);
        int b2 = __float2int_rn(r * inv * 128.0f);
        g_A1l[(size_t)row * SH + s] = (char)b1;
        g_A2l[(size_t)row * SH + s] = (char)b2;
    }
}

// fold + per-row quantize of x. Block: (dtile of 32, batch). smem 576x33 f32.
__global__ __launch_bounds__(256) void foldquant_x(const float* __restrict__ x) {
    extern __shared__ float xs[];   // [576][33]
    int d0 = blockIdx.x * 32;
    int b  = blockIdx.y;
    int tid = threadIdx.x;
    int lane = tid & 31, wid = tid >> 5;

    for (int s = wid; s < S_DIM; s += 8)
        xs[s * 33 + lane] = x[((size_t)b * S_DIM + s) * D_DIM + d0 + lane];
    __syncthreads();

    int row = tid >> 2;          // 0..63: p = row>>5, dcol = row&31
    int q   = tid & 3;
    int p = row >> 5, dcol = row & 31;
    float sgn = (p == 0) ? 1.0f : -1.0f;

    float m = 0.0f;
    #pragma unroll 4
    for (int k = 0; k < 72; k++) {
        int s = q * 72 + k;
        float v = xs[s * 33 + dcol] + sgn * xs[(575 - s) * 33 + dcol];
        m = fmaxf(m, fabsf(v));
    }
    m = fmaxf(m, __shfl_xor_sync(0xFFFFFFFF, m, 1));
    m = fmaxf(m, __shfl_xor_sync(0xFFFFFFFF, m, 2));
    float S = fmaxf(m, 1e-30f) / 127.0f;
    float inv = 127.0f / fmaxf(m, 1e-30f);
    size_t rowIdx = (size_t)(p * B_BATCH + b) * D_DIM + d0 + dcol;
    if (q == 0) g_SB[rowIdx] = S;

    size_t base = rowIdx * SH + q * 72;
    uint32_t* o1 = (uint32_t*)(g_B1l + base);
    uint32_t* o2 = (uint32_t*)(g_B2l + base);
    #pragma unroll 2
    for (int g = 0; g < 18; g++) {
        uint32_t w1 = 0, w2 = 0;
        #pragma unroll
        for (int i = 0; i < 4; i++) {
            int s = q * 72 + g * 4 + i;
            float v = xs[s * 33 + dcol] + sgn * xs[(575 - s) * 33 + dcol];
            int b1 = __float2int_rn(v * inv);
            b1 = max(-127, min(127, b1));
            float r = fmaf((float)-b1, S, v);
            int b2 = __float2int_rn(r * inv * 128.0f);
            w1 |= ((uint32_t)(uint8_t)(char)b1) << (8 * i);
            w2 |= ((uint32_t)(uint8_t)(char)b2) << (8 * i);
        }
        o1[g] = w1;
        o2[g] = w2;
    }
}

// ---------------- persistent IMMA GEMM ----------------
// Per tile: 9 chunk-iters of 96 B-of-K:
//   j 0..2: A1*B2 (k0=96j)   } term2 (scale Sa*Sb/128), merged after j==5
//   j 3..5: A2*B1            }
//   j 6..8: A1*B1              term1 (scale Sa*Sb),     merged after j==8
#define STAGE_BYTES 32768           // A 16KB + B 16KB (128 rows x 128B stride, 96B used)
#define SMEM_G      (3 * STAGE_BYTES)
#define KITERS      9

struct LdCtx {
    const char *pA1, *pA2, *pB1, *pB2;
};

__device__ __forceinline__ void set_ctx(LdCtx& c, int t) {
    int x = t & 7;
    int y = (t >> 3) % 10;
    int b = t / 80;
    int p = y / 5;
    int rowBase = (y % 5) * 128;
    int colBase = x * 128;
    size_t aoff = ((size_t)p * AROWS + rowBase) * SH;
    size_t boff = ((size_t)(p * B_BATCH + b) * D_DIM + colBase) * SH;
    c.pA1 = g_A1l + aoff;
    c.pA2 = g_A2l + aoff;
    c.pB1 = g_B1l + boff;
    c.pB2 = g_B2l + boff;
}

__device__ __forceinline__ void load_stage(uint32_t sbase, int slot, int j,
                                           const LdCtx& c, int tid) {
    int t  = j / 3;
    int k0 = (j - t * 3) * 96;
    const char* Asrc = (t == 1) ? c.pA2 : c.pA1;
    const char* Bsrc = (t == 0) ? c.pB2 : c.pB1;
    uint32_t sA = sbase + slot * STAGE_BYTES;
    uint32_t sB = sA + 16384;
    #pragma unroll
    for (int q = 0; q < 3; q++) {
        int cix = tid + q * 512;
        if (cix < 768) {
            int row = cix / 6, ku = cix % 6;
            cp16(sA + SWZ(row * 128 + ku * 16), Asrc + (size_t)row * SH + k0 + ku * 16);
        } else {
            int cix2 = cix - 768;
            int row = cix2 / 6, ku = cix2 % 6;
            cp16(sB + SWZ(row * 128 + ku * 16), Bsrc + (size_t)row * SH + k0 + ku * 16);
        }
    }
}

__global__ __launch_bounds__(512, 1) void gemm_imma(float* __restrict__ out_trunc,
                                                    int L, int nM) {
    extern __shared__ char dsm[];
    uint32_t sbase = smem_u32(dsm);
    const int tid  = threadIdx.x;
    const int warp = tid >> 5;
    const int lane = tid & 31;
    const int stride = gridDim.x;

    const int mBase = (warp & 3) * 32;
    const int nBase = (warp >> 2) * 32;
    const int aRow  = lane & 15;
    const int aColB = (lane >> 4) * 16;
    const int bRow  = (lane & 7) + ((lane >> 4) & 1) * 8;
    const int bColB = ((lane >> 3) & 1) * 16;

    // load-side state, 2 iterations ahead
    int t_ld = blockIdx.x;
    int j_ld = 0;
    int slot_ld = 0;
    LdCtx ctx;
    if (t_ld < NTILES) set_ctx(ctx, t_ld);

    #pragma unroll
    for (int q = 0; q < 2; q++) {
        if (t_ld < NTILES) load_stage(sbase, slot_ld, j_ld, ctx, tid);
        CP_COMMIT();
        slot_ld = (slot_ld == 2) ? 0 : slot_ld + 1;
        if (++j_ld == KITERS) {
            j_ld = 0; t_ld += stride;
            if (t_ld < NTILES) set_ctx(ctx, t_ld);
        }
    }

    int slot_cp = 0;
    for (int t_cp = blockIdx.x; t_cp < NTILES; t_cp += stride) {
        // tile decode
        int xx = t_cp & 7;
        int yy = (t_cp >> 3) % 10;
        int bb = t_cp / 80;
        int pp = yy / 5;
        int rowBase = (yy % 5) * 128;
        int colBase = xx * 128;

        float accf[2][4][4];
        int   acci[2][4][4];
        #pragma unroll
        for (int mt = 0; mt < 2; mt++)
            #pragma unroll
            for (int nt = 0; nt < 4; nt++)
                #pragma unroll
                for (int i = 0; i < 4; i++) { accf[mt][nt][i] = 0.0f; acci[mt][nt][i] = 0; }

        for (int j = 0; j < KITERS; j++) {
            CP_WAIT1();
            __syncthreads();

            uint32_t sA = sbase + slot_cp * STAGE_BYTES;
            uint32_t sB = sA + 16384;

            #pragma unroll
            for (int ks = 0; ks < 3; ks++) {
                uint32_t afr[2][4];
                #pragma unroll
                for (int mt = 0; mt < 2; mt++) {
                    int off = (mBase + mt * 16 + aRow) * 128 + ks * 32 + aColB;
                    ldsm_x4(afr[mt][0], afr[mt][1], afr[mt][2], afr[mt][3],
                            sA + SWZ(off));
                }
                uint32_t bfr[8];
                #pragma unroll
                for (int nt2 = 0; nt2 < 2; nt2++) {
                    int off = (nBase + nt2 * 16 + bRow) * 128 + ks * 32 + bColB;
                    ldsm_x4(bfr[nt2 * 4 + 0], bfr[nt2 * 4 + 1],
                            bfr[nt2 * 4 + 2], bfr[nt2 * 4 + 3], sB + SWZ(off));
                }
                #pragma unroll
                for (int mt = 0; mt < 2; mt++)
                    #pragma unroll
                    for (int nt = 0; nt < 4; nt++)
                        imma16832(acci[mt][nt], afr[mt], bfr[nt * 2], bfr[nt * 2 + 1]);
            }

            // feed pipeline (2 ahead)
            if (t_ld < NTILES) load_stage(sbase, slot_ld, j_ld, ctx, tid);
            CP_COMMIT();
            slot_ld = (slot_ld == 2) ? 0 : slot_ld + 1;
            if (++j_ld == KITERS) {
                j_ld = 0; t_ld += stride;
                if (t_ld < NTILES) set_ctx(ctx, t_ld);
            }
            slot_cp = (slot_cp == 2) ? 0 : slot_cp + 1;

            // term-boundary merge: int32 -> float with per-row/col scales
            if (j == 5 || j == 8) {
                float mul = (j == 5) ? (1.0f / 128.0f) : 1.0f;
                float sa[2][2], sb[4][2];
                #pragma unroll
                for (int mt = 0; mt < 2; mt++)
                    #pragma unroll
                    for (int h = 0; h < 2; h++) {
                        int r = rowBase + mBase + mt * 16 + (lane >> 2) + h * 8;
                        sa[mt][h] = g_SA[pp * AROWS + r] * mul;
                    }
                #pragma unroll
                for (int nt = 0; nt < 4; nt++)
                    #pragma unroll
                    for (int i2 = 0; i2 < 2; i2++) {
                        int ccol = colBase + nBase + nt * 8 + (lane & 3) * 2 + i2;
                        sb[nt][i2] = g_SB[(size_t)(pp * B_BATCH + bb) * D_DIM + ccol];
                    }
                #pragma unroll
                for (int mt = 0; mt < 2; mt++)
                    #pragma unroll
                    for (int nt = 0; nt < 4; nt++)
                        #pragma unroll
                        for (int h = 0; h < 2; h++)
                            #pragma unroll
                            for (int i2 = 0; i2 < 2; i2++) {
                                int q2 = h * 2 + i2;
                                accf[mt][nt][q2] = fmaf(
                                    (float)acci[mt][nt][q2], sa[mt][h] * sb[nt][i2],
                                    accf[mt][nt][q2]);
                                acci[mt][nt][q2] = 0;
                            }
            }
        }

        // ---- epilogue ----
        int nT = (L + 1 - pp) >> 1;
        float* ybase = g_y + ((size_t)pp * B_BATCH + bb) * SH * D_DIM;

        #pragma unroll
        for (int mt = 0; mt < 2; mt++) {
            #pragma unroll
            for (int nt = 0; nt < 4; nt++) {
                int rA = rowBase + mBase + mt * 16 + (lane >> 2);
                int cc = colBase + nBase + nt * 8 + (lane & 3) * 2;
                #pragma unroll
                for (int h = 0; h < 2; h++) {
                    int r = rA + h * 8;
                    float2 v = make_float2(accf[mt][nt][h * 2 + 0],
                                           accf[mt][nt][h * 2 + 1]);
                    if (r < nT) {
                        int tr = 2 * r + pp;
                        *reinterpret_cast<float2*>(
                            &out_trunc[((size_t)bb * L + tr) * D_DIM + cc]) = v;
                    } else if (r >= MOFF && r < MOFF + nM) {
                        *reinterpret_cast<float2*>(
                            &ybase[(size_t)(r - MOFF) * D_DIM + cc]) = v;
                    }
                }
            }
        }
    }
}

// recon[l] = fp16(ye+yo), recon[L-1-l] = fp16(ye-yo)
__global__ void butterfly(float* __restrict__ out_recon, int L, int nM) {
    int idx = blockIdx.x * blockDim.x + threadIdx.x;
    int total = B_BATCH * nM * (D_DIM / 4);
    if (idx >= total) return;
    int d4 = idx & (D_DIM / 4 - 1);
    int l  = (idx / (D_DIM / 4)) % nM;
    int b  = idx / ((D_DIM / 4) * nM);
    int d  = d4 * 4;
    const float4 ye = *reinterpret_cast<const float4*>(
        &g_y[((size_t)b * SH + l) * D_DIM + d]);
    const float4 yo = *reinterpret_cast<const float4*>(
        &g_y[((size_t)(B_BATCH + b) * SH + l) * D_DIM + d]);
    float4 s, f;
    s.x = __half2float(__float2half_rn(ye.x + yo.x));
    s.y = __half2float(__float2half_rn(ye.y + yo.y));
    s.z = __half2float(__float2half_rn(ye.z + yo.z));
    s.w = __half2float(__float2half_rn(ye.w + yo.w));
    *reinterpret_cast<float4*>(&out_recon[((size_t)b * L + l) * D_DIM + d]) = s;
    int l2 = L - 1 - l;
    if (l2 != l) {
        f.x = __half2float(__float2half_rn(ye.x - yo.x));
        f.y = __half2float(__float2half_rn(ye.y - yo.y));
        f.z = __half2float(__float2half_rn(ye.z - yo.z));
        f.w = __half2float(__float2half_rn(ye.w - yo.w));
        *reinterpret_cast<float4*>(&out_recon[((size_t)b * L + l2) * D_DIM + d]) = f;
    }
}

// ---------------- launch ----------------
static cudaStream_t g_s2 = 0;
static cudaEvent_t  g_evFork = 0, g_evJoin = 0;

#define SMEM_FOLD (S_DIM * 33 * 4)

extern "C" void kernel_launch(void* const* d_in, const int* in_sizes, int n_in,
                              void* d_out, int out_size) {
    const float* x = (const float*)d_in[0];
    const int L  = out_size / (2 * B_BATCH * D_DIM);
    const int nM = (L + 1) >> 1;

    float* out_recon = (float*)d_out;
    float* out_trunc = (float*)d_out + (size_t)B_BATCH * L * D_DIM;

    if (!g_s2) {     // first call is the uncaptured correctness run
        cudaStreamCreateWithFlags(&g_s2, cudaStreamNonBlocking);
        cudaEventCreateWithFlags(&g_evFork, cudaEventDisableTiming);
        cudaEventCreateWithFlags(&g_evJoin, cudaEventDisableTiming);
        cudaFuncSetAttribute(gemm_imma, cudaFuncAttributeMaxDynamicSharedMemorySize,
                             SMEM_G);
        cudaFuncSetAttribute(foldquant_x, cudaFuncAttributeMaxDynamicSharedMemorySize,
                             SMEM_FOLD);
    }

    // fork: A-side build chain on side stream, B-side fold+quant on capture stream
    cudaEventRecord(g_evFork, 0);
    cudaStreamWaitEvent(g_s2, g_evFork, 0);

    prep_basis<<<512, 256, 0, g_s2>>>(L);
    build_M2<<<dim3(SH / 32, (nM + 31) / 32, 2), dim3(16, 16), 0, g_s2>>>(L, nM);
    quantize_A<<<(2 * AROWS + 7) / 8, 256, 0, g_s2>>>();

    foldquant_x<<<dim3(32, B_BATCH), 256, SMEM_FOLD>>>(x);

    // join
    cudaEventRecord(g_evJoin, g_s2);
    cudaStreamWaitEvent(0, g_evJoin, 0);

    gemm_imma<<<GRID_P, 512, SMEM_G>>>(out_trunc, L, nM);

    int btot = B_BATCH * nM * (D_DIM / 4);
    butterfly<<<(btot + 255) / 256, 256>>>(out_recon, L, nM);
}